// round 13
// baseline (speedup 1.0000x reference)
#include <cuda_runtime.h>
#include <cuda_bf16.h>
#include <cstdint>
#include <cstddef>

#define NN    10000
#define KP    10112          // 79 * 128  (K padded, fp8 bytes per row)
#define MPAD  10112          // 79 * 128
#define CPAD  2304           // 9 * 256
#define CDIM  2112           // 66 * 32
#define KT_   79             // K tiles of 128
#define BATCH 32
#define HID   64
#define DFE   66
#define STAGE_BYTES 49152    // A 16KB + B 32KB

// scales: A*2^12, x*2^4, x1*2^6
#define SC_X1   (1.f/65536.f)    // acc -> x1          (2^-16)
#define SC_X1Q  (1.f/1024.f)     // acc -> fp8(x1*64)  (2^-10)
#define SC_X2   (1.f/131072.f)   // 2*acc*2^-18        (2^-17)

// ---------------- scratch (__device__ globals; zero-initialized; pads never written) ----------------
__device__ unsigned char g_A8 [(size_t)MPAD * KP];    // A fp8 [m][k]  (x 2^12)
__device__ unsigned char g_XTa[(size_t)CPAD * KP];    // X^T fp8 [c][k] (x 2^4)
__device__ unsigned char g_XTb[(size_t)CPAD * KP];    // x1^T fp8 [c][k] (x 2^6)
__device__ float g_x0[(size_t)NN * CDIM];
__device__ float g_x1[(size_t)NN * CDIM];
__device__ float g_x2[(size_t)NN * CDIM];
__device__ float g_u [(size_t)BATCH * NN * HID];
__device__ float g_rs[(size_t)BATCH * NN * HID];

// ---------------- helpers ----------------
__device__ __forceinline__ uint32_t s2u(const void* p) {
    uint32_t a;
    asm("{ .reg .u64 t; cvta.to.shared.u64 t, %1; cvt.u32.u64 %0, t; }" : "=r"(a) : "l"(p));
    return a;
}
__device__ __forceinline__ void cp16(uint32_t dst, const void* src) {
    asm volatile("cp.async.cg.shared.global [%0], [%1], 16;\n" :: "r"(dst), "l"(src));
}
__device__ __forceinline__ void cp_commit() { asm volatile("cp.async.commit_group;\n"); }
template <int N>
__device__ __forceinline__ void cp_wait() { asm volatile("cp.async.wait_group %0;\n" :: "n"(N)); }

__device__ __forceinline__ void ldsm4(uint32_t* r, uint32_t addr) {
    asm volatile("ldmatrix.sync.aligned.m8n8.x4.shared.b16 {%0,%1,%2,%3}, [%4];"
                 : "=r"(r[0]), "=r"(r[1]), "=r"(r[2]), "=r"(r[3]) : "r"(addr));
}
__device__ __forceinline__ void mma_f8(float* c, const uint32_t* a, const uint32_t* b) {
    asm volatile("mma.sync.aligned.m16n8k32.row.col.f32.e4m3.e4m3.f32 "
                 "{%0,%1,%2,%3}, {%4,%5,%6,%7}, {%8,%9}, {%0,%1,%2,%3};"
                 : "+f"(c[0]), "+f"(c[1]), "+f"(c[2]), "+f"(c[3])
                 : "r"(a[0]), "r"(a[1]), "r"(a[2]), "r"(a[3]), "r"(b[0]), "r"(b[1]));
}
// packs: high byte = hi, low byte = lo
__device__ __forceinline__ unsigned short cvt_e4m3x2(float lo, float hi) {
    unsigned short r;
    asm("cvt.rn.satfinite.e4m3x2.f32 %0, %1, %2;" : "=h"(r) : "f"(hi), "f"(lo));
    return r;
}
__device__ __forceinline__ unsigned char fp8b(float v) {
    return (unsigned char)(cvt_e4m3x2(v, 0.f) & 0xFF);
}
__device__ __forceinline__ float sigf(float x) { return 1.f / (1.f + __expf(-x)); }

// ---------------- A fp32 -> fp8 (x 4096), stride KP ----------------
__global__ void conv_A8(const float* __restrict__ A) {
    int m = blockIdx.y;
    int id = blockIdx.x * blockDim.x + threadIdx.x;   // 0..1279
    if (id >= 1250) return;
    const float4* src = (const float4*)(A + (size_t)m * NN) + id * 2;
    float4 f0 = src[0], f1 = src[1];
    const float S = 4096.f;
    unsigned short s0 = cvt_e4m3x2(f0.x * S, f0.y * S);
    unsigned short s1 = cvt_e4m3x2(f0.z * S, f0.w * S);
    unsigned short s2 = cvt_e4m3x2(f1.x * S, f1.y * S);
    unsigned short s3 = cvt_e4m3x2(f1.z * S, f1.w * S);
    uint2 o;
    o.x = (uint32_t)s0 | ((uint32_t)s1 << 16);
    o.y = (uint32_t)s2 | ((uint32_t)s3 << 16);
    *(uint2*)(g_A8 + (size_t)m * KP + id * 8) = o;
}

// ---------------- build g_x0 fp32 [n][c] ----------------
__global__ void build_x0_k(const float* __restrict__ inputs, const float* __restrict__ states) {
    int n = blockIdx.x, tid = threadIdx.x;
    __shared__ float s[64][33];
    for (int i = tid; i < BATCH * HID; i += 256) {
        int b = i >> 6, h = i & 63;
        s[h][b] = states[((size_t)b * NN + n) * HID + h];
    }
    __syncthreads();
    size_t r0 = (size_t)n * CDIM;
    for (int c = tid; c < CDIM; c += 256) {
        int d = c >> 5, b = c & 31;
        g_x0[r0 + c] = (d < 2) ? inputs[((size_t)b * NN + n) * 2 + d] : s[d - 2][b];
    }
}

// ---------------- update state cols of g_x0 from g_rs ----------------
__global__ void update_x0_k() {
    int n = blockIdx.x, tid = threadIdx.x;
    __shared__ float s[64][33];
    for (int i = tid; i < BATCH * HID; i += 256) {
        int b = i >> 6, h = i & 63;
        s[h][b] = g_rs[((size_t)b * NN + n) * HID + h];
    }
    __syncthreads();
    size_t r0 = (size_t)n * CDIM;
    for (int c = 64 + tid; c < CDIM; c += 256) {
        int d = c >> 5, b = c & 31;
        g_x0[r0 + c] = s[d - 2][b];
    }
}

// ---------------- build g_XTa fp8 [c][k] (x 16): PHASE 0 full, PHASE 1 state rows from g_rs ----------------
template <int PHASE>
__global__ void build_XT_k(const float* __restrict__ inputs, const float* __restrict__ states) {
    const float* __restrict__ src = (PHASE == 0) ? states : g_rs;
    int n0 = blockIdx.x * 32, tid = threadIdx.x;
    __shared__ float t[64][33];
    const float S = 16.f;

    if (PHASE == 0) {
        for (int i = tid; i < 64 * 32; i += 256) {
            int c = i >> 5, nr = i & 31;
            int n = n0 + nr;
            if (n < NN) {
                int d = c >> 5, b = c & 31;
                g_XTa[(size_t)c * KP + n] = fp8b(inputs[((size_t)b * NN + n) * 2 + d] * S);
            }
        }
    }

    for (int b = 0; b < BATCH; ++b) {
        // FIXED: load ALL 64 h-rows (512 float4 loads, 2 per thread).
        // Previous version used nr=tid>>3,h4=tid&7 which only filled t[0..31][*],
        // leaving t[32..63][*] uninitialized -> half of every state feature garbage.
#pragma unroll
        for (int rep = 0; rep < 2; ++rep) {
            int id = tid + rep * 256;
            int nr = id >> 4, h4 = id & 15;
            int n = n0 + nr;
            if (n < NN) {
                float4 v = *(const float4*)&src[((size_t)b * NN + n) * HID + h4 * 4];
                t[h4 * 4 + 0][nr] = v.x; t[h4 * 4 + 1][nr] = v.y;
                t[h4 * 4 + 2][nr] = v.z; t[h4 * 4 + 3][nr] = v.w;
            }
        }
        __syncthreads();
        int h = tid >> 2, q = tid & 3;
        int nb = n0 + q * 8;
        if (nb < NN) {   // NN % 8 == 0: chunk fully valid or fully invalid
            unsigned short s0 = cvt_e4m3x2(t[h][q*8+0]*S, t[h][q*8+1]*S);
            unsigned short s1 = cvt_e4m3x2(t[h][q*8+2]*S, t[h][q*8+3]*S);
            unsigned short s2 = cvt_e4m3x2(t[h][q*8+4]*S, t[h][q*8+5]*S);
            unsigned short s3 = cvt_e4m3x2(t[h][q*8+6]*S, t[h][q*8+7]*S);
            uint2 o;
            o.x = (uint32_t)s0 | ((uint32_t)s1 << 16);
            o.y = (uint32_t)s2 | ((uint32_t)s3 << 16);
            *(uint2*)(g_XTa + (size_t)((h + 2) * 32 + b) * KP + nb) = o;
        }
        __syncthreads();
    }
}

// ---------------- fp8 mma GEMM: D[128 x 256] tile of A @ X ----------------
// MODE 0: B = g_XTa; writes fp32 x1 -> g_x1 and fp8 x1^T -> g_XTb
// MODE 1: B = g_XTb; writes (2*acc*sc - x0) -> g_x2
template <int MODE>
__global__ __launch_bounds__(256, 1) void gemm_f8() {
    extern __shared__ char dyn[];
    const unsigned char* __restrict__ Xsrc = (MODE == 0) ? g_XTa : g_XTb;

    const int tid = threadIdx.x;
    const int wid = tid >> 5, lid = tid & 31;
    const int wm = wid >> 2, wn = wid & 3;        // 2 x 4 warp grid, 64x64 warp tiles
    const int m0 = blockIdx.y * 128;
    const int c0 = blockIdx.x * 256;
    const uint32_t sbase = s2u(dyn);

    float acc[4][8][4];
#pragma unroll
    for (int i = 0; i < 4; ++i)
#pragma unroll
        for (int j = 0; j < 8; ++j)
#pragma unroll
            for (int q = 0; q < 4; ++q) acc[i][j][q] = 0.f;

    auto load_stage = [&](int s, int kt) {
        const uint32_t As = sbase + s * STAGE_BYTES;
        const uint32_t Bs = As + 16384;
        const unsigned char* ap = g_A8 + (size_t)m0 * KP + kt * 128;
        const unsigned char* bp = Xsrc + (size_t)c0 * KP + kt * 128;
        // A: 128 rows x 8 chunks (16B)
#pragma unroll
        for (int i = 0; i < 4; ++i) {
            int id = tid + 256 * i;
            int r = id >> 3, c = id & 7;
            cp16(As + r * 128 + (((c ^ (r & 7)) << 4)), ap + (size_t)r * KP + c * 16);
        }
        // B: 256 rows x 8 chunks (16B)
#pragma unroll
        for (int i = 0; i < 8; ++i) {
            int id = tid + 256 * i;
            int r = id >> 3, c = id & 7;
            cp16(Bs + r * 128 + (((c ^ (r & 7)) << 4)), bp + (size_t)r * KP + c * 16);
        }
    };

    const int lrow = lid & 15, lchk = lid >> 4;                 // A ldsm lanes
    const int nloc = (lid & 7) + ((lid & 16) >> 1);             // B ldsm lanes
    const int bsel = (lid >> 3) & 1;

    auto compute = [&](int s) {
        const uint32_t sA = sbase + s * STAGE_BYTES;
        const uint32_t sB = sA + 16384;
#pragma unroll
        for (int kk = 0; kk < 4; ++kk) {
            uint32_t af[4][4];
#pragma unroll
            for (int i = 0; i < 4; ++i) {
                int r = wm * 64 + i * 16 + lrow;
                int c = kk * 2 + lchk;
                ldsm4(af[i], sA + r * 128 + (((c ^ (r & 7)) << 4)));
            }
            uint32_t bf[8][2];
#pragma unroll
            for (int p = 0; p < 4; ++p) {
                int r = wn * 64 + p * 16 + nloc;
                int c = kk * 2 + bsel;
                uint32_t rr[4];
                ldsm4(rr, sB + r * 128 + (((c ^ (r & 7)) << 4)));
                bf[2*p][0] = rr[0]; bf[2*p][1] = rr[1];
                bf[2*p+1][0] = rr[2]; bf[2*p+1][1] = rr[3];
            }
#pragma unroll
            for (int i = 0; i < 4; ++i)
#pragma unroll
                for (int j = 0; j < 8; ++j)
                    mma_f8(acc[i][j], af[i], bf[j]);
        }
    };

    // prologue
    load_stage(0, 0); cp_commit();
    load_stage(1, 1); cp_commit();

    for (int kt = 0; kt < KT_; ++kt) {
        cp_wait<1>();
        __syncthreads();
        if (kt + 2 < KT_) load_stage((kt + 2) % 3, kt + 2);
        cp_commit();
        compute(kt % 3);
    }

    // ---------------- fused epilogue ----------------
    const int q = lid >> 2, t4 = lid & 3;
    char* stT = dyn + STAGE_BYTES + wid * 6144;   // stage1 region; last compute used stage (78%3)=0

#pragma unroll
    for (int i = 0; i < 4; ++i) {
        const int ra = m0 + wm * 64 + i * 16 + q;
        const int rb = ra + 8;
#pragma unroll
        for (int j = 0; j < 8; ++j) {
            const int cc = c0 + wn * 64 + j * 8 + t4 * 2;
            const float* a = acc[i][j];
            if (MODE == 0) {
                if (cc < CDIM) {
                    if (ra < NN)
                        *(float2*)(g_x1 + (size_t)ra * CDIM + cc) =
                            make_float2(a[0] * SC_X1, a[1] * SC_X1);
                    if (rb < NN)
                        *(float2*)(g_x1 + (size_t)rb * CDIM + cc) =
                            make_float2(a[2] * SC_X1, a[3] * SC_X1);
                }
                // stage fp8(x1 * 64) transposed, per-warp 64x64 tile (rows c, stride 96)
                const int cl = j * 8 + t4 * 2;
                const int ml = i * 16 + q;
                stT[(size_t)cl * 96 + ml]           = fp8b(a[0] * SC_X1Q);
                stT[(size_t)(cl + 1) * 96 + ml]     = fp8b(a[1] * SC_X1Q);
                stT[(size_t)cl * 96 + ml + 8]       = fp8b(a[2] * SC_X1Q);
                stT[(size_t)(cl + 1) * 96 + ml + 8] = fp8b(a[3] * SC_X1Q);
            } else {
                if (cc < CDIM) {
                    if (ra < NN) {
                        float2 x = *(const float2*)(g_x0 + (size_t)ra * CDIM + cc);
                        *(float2*)(g_x2 + (size_t)ra * CDIM + cc) =
                            make_float2(a[0] * SC_X2 - x.x, a[1] * SC_X2 - x.y);
                    }
                    if (rb < NN) {
                        float2 x = *(const float2*)(g_x0 + (size_t)rb * CDIM + cc);
                        *(float2*)(g_x2 + (size_t)rb * CDIM + cc) =
                            make_float2(a[2] * SC_X2 - x.x, a[3] * SC_X2 - x.y);
                    }
                }
            }
        }
    }

    if (MODE == 0) {
        __syncwarp();
        // write back x1^T: lane handles c-rows lid*2, lid*2+1 of the 64x64 staged tile
#pragma unroll
        for (int rr = 0; rr < 2; ++rr) {
            int cl = lid * 2 + rr;
            int c = c0 + wn * 64 + cl;
            if (c < CDIM) {
                const uint4* srcp = (const uint4*)(stT + (size_t)cl * 96);
                uint4* dstp = (uint4*)(g_XTb + (size_t)c * KP + m0 + wm * 64);
#pragma unroll
                for (int v = 0; v < 4; ++v) dstp[v] = srcp[v];
            }
        }
    }
}

// ---------------- ru = sigmoid(xk @ Wru + bru); emit u and r*states ----------------
__global__ __launch_bounds__(256) void ru_kernel(const float* __restrict__ Wru,
                                                 const float* __restrict__ bru,
                                                 const float* __restrict__ states) {
    int n = blockIdx.x, tid = threadIdx.x;
    __shared__ float xr[3][CDIM];
    {
        const float4* p0 = (const float4*)(g_x0 + (size_t)n * CDIM);
        const float4* p1 = (const float4*)(g_x1 + (size_t)n * CDIM);
        const float4* p2 = (const float4*)(g_x2 + (size_t)n * CDIM);
        for (int i = tid; i < CDIM / 4; i += 256) {
            ((float4*)xr[0])[i] = p0[i];
            ((float4*)xr[1])[i] = p1[i];
            ((float4*)xr[2])[i] = p2[i];
        }
    }
    __syncthreads();

    const int hq = tid & 31, bg = tid >> 5;
    const int h0 = hq * 4;
    float4 acc[4];
    float4 bb = *(const float4*)&bru[h0];
#pragma unroll
    for (int j = 0; j < 4; ++j) acc[j] = bb;

    for (int d = 0; d < DFE; ++d) {
        float4 w0 = *(const float4*)&Wru[(d * 3 + 0) * 128 + h0];
        float4 w1 = *(const float4*)&Wru[(d * 3 + 1) * 128 + h0];
        float4 w2 = *(const float4*)&Wru[(d * 3 + 2) * 128 + h0];
#pragma unroll
        for (int j = 0; j < 4; ++j) {
            int b = bg + 8 * j;
            float x0v = xr[0][d * 32 + b];
            float x1v = xr[1][d * 32 + b];
            float x2v = xr[2][d * 32 + b];
            acc[j].x += x0v * w0.x + x1v * w1.x + x2v * w2.x;
            acc[j].y += x0v * w0.y + x1v * w1.y + x2v * w2.y;
            acc[j].z += x0v * w0.z + x1v * w1.z + x2v * w2.z;
            acc[j].w += x0v * w0.w + x1v * w1.w + x2v * w2.w;
        }
    }

#pragma unroll
    for (int j = 0; j < 4; ++j) {
        int b = bg + 8 * j;
        size_t base = ((size_t)b * NN + n) * HID;
        float4 s4;
        s4.x = sigf(acc[j].x); s4.y = sigf(acc[j].y);
        s4.z = sigf(acc[j].z); s4.w = sigf(acc[j].w);
        if (h0 < 64) {
            float4 sv = *(const float4*)&states[base + h0];
            float4 rs;
            rs.x = s4.x * sv.x; rs.y = s4.y * sv.y;
            rs.z = s4.z * sv.z; rs.w = s4.w * sv.w;
            *(float4*)&g_rs[base + h0] = rs;
        } else {
            *(float4*)&g_u[base + h0 - 64] = s4;
        }
    }
}

// ---------------- c = tanh(xk @ Wc + bc); out = u*s + (1-u)*c ----------------
__global__ __launch_bounds__(256) void out_kernel(const float* __restrict__ Wc,
                                                  const float* __restrict__ bc,
                                                  const float* __restrict__ states,
                                                  float* __restrict__ out) {
    int n = blockIdx.x, tid = threadIdx.x;
    __shared__ float xr[3][CDIM];
    {
        const float4* p0 = (const float4*)(g_x0 + (size_t)n * CDIM);
        const float4* p1 = (const float4*)(g_x1 + (size_t)n * CDIM);
        const float4* p2 = (const float4*)(g_x2 + (size_t)n * CDIM);
        for (int i = tid; i < CDIM / 4; i += 256) {
            ((float4*)xr[0])[i] = p0[i];
            ((float4*)xr[1])[i] = p1[i];
            ((float4*)xr[2])[i] = p2[i];
        }
    }
    __syncthreads();

    const int hq = tid & 15, bg = tid >> 4;
    const int h0 = hq * 4;
    float4 acc[2];
    float4 bb = *(const float4*)&bc[h0];
    acc[0] = bb; acc[1] = bb;

    for (int d = 0; d < DFE; ++d) {
        float4 w0 = *(const float4*)&Wc[(d * 3 + 0) * 64 + h0];
        float4 w1 = *(const float4*)&Wc[(d * 3 + 1) * 64 + h0];
        float4 w2 = *(const float4*)&Wc[(d * 3 + 2) * 64 + h0];
#pragma unroll
        for (int j = 0; j < 2; ++j) {
            int b = bg + 16 * j;
            float x0v = xr[0][d * 32 + b];
            float x1v = xr[1][d * 32 + b];
            float x2v = xr[2][d * 32 + b];
            acc[j].x += x0v * w0.x + x1v * w1.x + x2v * w2.x;
            acc[j].y += x0v * w0.y + x1v * w1.y + x2v * w2.y;
            acc[j].z += x0v * w0.z + x1v * w1.z + x2v * w2.z;
            acc[j].w += x0v * w0.w + x1v * w1.w + x2v * w2.w;
        }
    }

#pragma unroll
    for (int j = 0; j < 2; ++j) {
        int b = bg + 16 * j;
        size_t base = ((size_t)b * NN + n) * HID + h0;
        float4 u4 = *(const float4*)&g_u[base];
        float4 sv = *(const float4*)&states[base];
        float4 o;
        float c0 = tanhf(acc[j].x), c1 = tanhf(acc[j].y),
              c2 = tanhf(acc[j].z), c3 = tanhf(acc[j].w);
        o.x = u4.x * sv.x + (1.f - u4.x) * c0;
        o.y = u4.y * sv.y + (1.f - u4.y) * c1;
        o.z = u4.z * sv.z + (1.f - u4.z) * c2;
        o.w = u4.w * sv.w + (1.f - u4.w) * c3;
        *(float4*)&out[base] = o;
    }
}

// ---------------- launcher ----------------
extern "C" void kernel_launch(void* const* d_in, const int* in_sizes, int n_in,
                              void* d_out, int out_size) {
    const float *inputs = nullptr, *states = nullptr, *A = nullptr;
    const float *Wru = nullptr, *bru = nullptr, *Wc = nullptr, *bc = nullptr;
    for (int i = 0; i < n_in; ++i) {
        const float* p = (const float*)d_in[i];
        switch (in_sizes[i]) {
            case 640000:    inputs = p; break;
            case 20480000:  states = p; break;
            case 100000000: A      = p; break;
            case 25344:     Wru    = p; break;
            case 128:       bru    = p; break;
            case 12672:     Wc     = p; break;
            case 64:        bc     = p; break;
            default: break;
        }
    }
    float* out = (float*)d_out;

    const int SMEMSZ = 3 * STAGE_BYTES;   // 147456
    cudaFuncSetAttribute(gemm_f8<0>, cudaFuncAttributeMaxDynamicSharedMemorySize, SMEMSZ);
    cudaFuncSetAttribute(gemm_f8<1>, cudaFuncAttributeMaxDynamicSharedMemorySize, SMEMSZ);

    conv_A8<<<dim3(5, NN), 256>>>(A);
    build_x0_k<<<NN, 256>>>(inputs, states);
    build_XT_k<0><<<313, 256>>>(inputs, states);

    dim3 g(CPAD / 256, MPAD / 128);       // 9 x 79
    gemm_f8<0><<<g, 256, SMEMSZ>>>();     // x1 = A @ x0   (+ fp8 x1^T)
    gemm_f8<1><<<g, 256, SMEMSZ>>>();     // x2 = 2*A@x1 - x0
    ru_kernel<<<NN, 256>>>(Wru, bru, states);
    update_x0_k<<<NN, 256>>>();
    build_XT_k<1><<<313, 256>>>(inputs, states);
    gemm_f8<0><<<g, 256, SMEMSZ>>>();     // x1' (+ fp8 x1'^T)
    gemm_f8<1><<<g, 256, SMEMSZ>>>();     // x2'
    out_kernel<<<NN, 256>>>(Wc, bc, states, out);
}

// round 14
// speedup vs baseline: 1.1493x; 1.1493x over previous
#include <cuda_runtime.h>
#include <cuda_bf16.h>
#include <cstdint>
#include <cstddef>

#define NN    10000
#define KP    10048          // 157 * 64  (K padded)
#define MPAD  10112          // 79 * 128  (M padded)
#define CPAD  2304           // 18 * 128  (feature dim padded)
#define CDIM  2112           // 66 * 32
#define KT_   157
#define BATCH 32
#define HID   64
#define DFE   66
#define STAGE_BYTES 32768    // A 16KB + B 16KB

// ---------------- scratch (__device__ globals; zero-initialized; pads never written) ----------------
__device__ __nv_bfloat16 g_Abf[(size_t)MPAD * KP];    // A bf16 [m][k]
__device__ __nv_bfloat16 g_Xa [(size_t)KP * CPAD];    // X bf16 [k][c]   (gconv input)
__device__ __nv_bfloat16 g_Xb [(size_t)KP * CPAD];    // A@X bf16 [k][c]
__device__ float g_x0[(size_t)NN * CDIM];
__device__ float g_x1[(size_t)NN * CDIM];
__device__ float g_x2[(size_t)NN * CDIM];
__device__ float g_u [(size_t)BATCH * NN * HID];
__device__ float g_rs[(size_t)BATCH * NN * HID];

// ---------------- helpers ----------------
__device__ __forceinline__ uint32_t s2u(const void* p) {
    uint32_t a;
    asm("{ .reg .u64 t; cvta.to.shared.u64 t, %1; cvt.u32.u64 %0, t; }" : "=r"(a) : "l"(p));
    return a;
}
__device__ __forceinline__ void cp16(uint32_t dst, const void* src) {
    asm volatile("cp.async.cg.shared.global [%0], [%1], 16;\n" :: "r"(dst), "l"(src));
}
__device__ __forceinline__ void cp_commit() { asm volatile("cp.async.commit_group;\n"); }
template <int N>
__device__ __forceinline__ void cp_wait() { asm volatile("cp.async.wait_group %0;\n" :: "n"(N)); }

__device__ __forceinline__ void ldsm4(uint32_t* r, uint32_t addr) {
    asm volatile("ldmatrix.sync.aligned.m8n8.x4.shared.b16 {%0,%1,%2,%3}, [%4];"
                 : "=r"(r[0]), "=r"(r[1]), "=r"(r[2]), "=r"(r[3]) : "r"(addr));
}
__device__ __forceinline__ void ldsm4t(uint32_t& r0, uint32_t& r1, uint32_t& r2, uint32_t& r3,
                                       uint32_t addr) {
    asm volatile("ldmatrix.sync.aligned.m8n8.x4.trans.shared.b16 {%0,%1,%2,%3}, [%4];"
                 : "=r"(r0), "=r"(r1), "=r"(r2), "=r"(r3) : "r"(addr));
}
__device__ __forceinline__ void mma16816(float* c, const uint32_t* a, const uint32_t* b) {
    asm volatile("mma.sync.aligned.m16n8k16.row.col.f32.bf16.bf16.f32 "
                 "{%0,%1,%2,%3}, {%4,%5,%6,%7}, {%8,%9}, {%0,%1,%2,%3};"
                 : "+f"(c[0]), "+f"(c[1]), "+f"(c[2]), "+f"(c[3])
                 : "r"(a[0]), "r"(a[1]), "r"(a[2]), "r"(a[3]), "r"(b[0]), "r"(b[1]));
}
__device__ __forceinline__ float sigf(float x) { return 1.f / (1.f + __expf(-x)); }

// ---------------- K1: A fp32 -> bf16 (stride KP; pads stay zero) ----------------
__global__ void conv_A(const float* __restrict__ A) {
    int m = blockIdx.y;
    int x4 = blockIdx.x * blockDim.x + threadIdx.x;   // 0..2559
    if (x4 >= NN / 4) return;
    float4 f = ((const float4*)(A + (size_t)m * NN))[x4];
    __nv_bfloat162* dst = (__nv_bfloat162*)(g_Abf + (size_t)m * KP + x4 * 4);
    dst[0] = __floats2bfloat162_rn(f.x, f.y);
    dst[1] = __floats2bfloat162_rn(f.z, f.w);
}

// ---------------- build g_x0 fp32 [n][c] and g_Xa bf16 [n][c] ----------------
__global__ void build_x0_k(const float* __restrict__ inputs, const float* __restrict__ states) {
    int n = blockIdx.x, tid = threadIdx.x;
    __shared__ float s[64][33];
    for (int i = tid; i < BATCH * HID; i += 256) {
        int b = i >> 6, h = i & 63;
        s[h][b] = states[((size_t)b * NN + n) * HID + h];
    }
    __syncthreads();
    size_t r0 = (size_t)n * CDIM, r1 = (size_t)n * CPAD;
    for (int c = tid; c < CDIM; c += 256) {
        int d = c >> 5, b = c & 31;
        float v = (d < 2) ? inputs[((size_t)b * NN + n) * 2 + d] : s[d - 2][b];
        g_x0[r0 + c] = v;
        g_Xa[r1 + c] = __float2bfloat16(v);
    }
}

// ---------------- update state cols of g_x0/g_Xa from g_rs ----------------
__global__ void update_x0_k() {
    int n = blockIdx.x, tid = threadIdx.x;
    __shared__ float s[64][33];
    for (int i = tid; i < BATCH * HID; i += 256) {
        int b = i >> 6, h = i & 63;
        s[h][b] = g_rs[((size_t)b * NN + n) * HID + h];
    }
    __syncthreads();
    size_t r0 = (size_t)n * CDIM, r1 = (size_t)n * CPAD;
    for (int c = 64 + tid; c < CDIM; c += 256) {
        int d = c >> 5, b = c & 31;
        float v = s[d - 2][b];
        g_x0[r0 + c] = v;
        g_Xa[r1 + c] = __float2bfloat16(v);
    }
}

// ---------------- mma.sync GEMM: D[128 x 128] tile of A @ X, 2 CTAs/SM ----------------
// MODE 0: X = g_Xa; writes fp32 -> g_x1 and bf16 -> g_Xb
// MODE 1: X = g_Xb; writes (2*acc - g_x0) -> g_x2
template <int MODE>
__global__ __launch_bounds__(256, 2) void gemm_mma() {
    extern __shared__ char dyn[];
    const __nv_bfloat16* __restrict__ Xsrc = (MODE == 0) ? g_Xa : g_Xb;

    const int tid = threadIdx.x;
    const int wid = tid >> 5, lid = tid & 31;
    const int wm = wid >> 2, wn = wid & 3;        // 2 x 4 warp grid, 64x32 warp tiles
    const int m0 = blockIdx.y * 128;
    const int c0 = blockIdx.x * 128;
    const uint32_t sbase = s2u(dyn);

    float acc[4][4][4];
#pragma unroll
    for (int i = 0; i < 4; ++i)
#pragma unroll
        for (int j = 0; j < 4; ++j)
#pragma unroll
            for (int q = 0; q < 4; ++q) acc[i][j][q] = 0.f;

    auto load_stage = [&](int s, int kt) {
        const uint32_t As = sbase + s * STAGE_BYTES;
        const uint32_t Bs = As + 16384;
        const __nv_bfloat16* ap = g_Abf + (size_t)m0 * KP + kt * 64;
        const __nv_bfloat16* bp = Xsrc + (size_t)(kt * 64) * CPAD + c0;
        // A: 128 rows x 8 chunks (16B) = 1024
#pragma unroll
        for (int i = 0; i < 4; ++i) {
            int id = tid + 256 * i;
            int r = id >> 3, c = id & 7;
            cp16(As + r * 128 + (((c ^ (r & 7)) << 4)), ap + (size_t)r * KP + c * 8);
        }
        // B: 64 rows x 16 chunks (16B) = 1024
#pragma unroll
        for (int i = 0; i < 4; ++i) {
            int id = tid + 256 * i;
            int r = id >> 4, c = id & 15;
            cp16(Bs + r * 256 + (((c ^ (r & 7)) << 4)), bp + (size_t)r * CPAD + c * 8);
        }
        cp_commit();
    };

    const int lrow = lid & 15, lchk = lid >> 4;
    const int xr = lrow & 7;

    auto compute = [&](int s) {
        const uint32_t sA = sbase + s * STAGE_BYTES;
        const uint32_t sB = sA + 16384;
#pragma unroll
        for (int kk = 0; kk < 4; ++kk) {
            uint32_t af[4][4];
#pragma unroll
            for (int i = 0; i < 4; ++i) {
                int r = wm * 64 + i * 16 + lrow;
                int c = kk * 2 + lchk;
                ldsm4(af[i], sA + r * 128 + (((c ^ (r & 7)) << 4)));
            }
            uint32_t bf[4][2];
#pragma unroll
            for (int p = 0; p < 2; ++p) {
                int r = kk * 16 + lrow;
                int c = wn * 4 + p * 2 + lchk;
                ldsm4t(bf[2*p][0], bf[2*p][1], bf[2*p+1][0], bf[2*p+1][1],
                       sB + r * 256 + (((c ^ xr) << 4)));
            }
#pragma unroll
            for (int i = 0; i < 4; ++i)
#pragma unroll
                for (int j = 0; j < 4; ++j)
                    mma16816(acc[i][j], af[i], bf[j]);
        }
    };

    // prologue: stages 0,1
    load_stage(0, 0);
    load_stage(1, 1);

    for (int kt = 0; kt < KT_; ++kt) {
        cp_wait<1>();
        __syncthreads();
        if (kt + 2 < KT_) load_stage((kt + 2) % 3, kt + 2);
        else cp_commit();
        compute(kt % 3);
        __syncthreads();
    }

    // ---------------- fused epilogue ----------------
    const int q = lid >> 2, t4 = lid & 3;
#pragma unroll
    for (int i = 0; i < 4; ++i) {
        const int ra = m0 + wm * 64 + i * 16 + q;   // row for c0,c1
        const int rb = ra + 8;                      // row for c2,c3
#pragma unroll
        for (int j = 0; j < 4; ++j) {
            const int cc = c0 + wn * 32 + j * 8 + t4 * 2;
            if (cc >= CDIM) continue;
            const float* a = acc[i][j];
            if (MODE == 0) {
                if (ra < NN) {
                    *(float2*)(g_x1 + (size_t)ra * CDIM + cc) = make_float2(a[0], a[1]);
                    *(__nv_bfloat162*)(g_Xb + (size_t)ra * CPAD + cc) =
                        __floats2bfloat162_rn(a[0], a[1]);
                }
                if (rb < NN) {
                    *(float2*)(g_x1 + (size_t)rb * CDIM + cc) = make_float2(a[2], a[3]);
                    *(__nv_bfloat162*)(g_Xb + (size_t)rb * CPAD + cc) =
                        __floats2bfloat162_rn(a[2], a[3]);
                }
            } else {
                if (ra < NN) {
                    float2 x = *(const float2*)(g_x0 + (size_t)ra * CDIM + cc);
                    *(float2*)(g_x2 + (size_t)ra * CDIM + cc) =
                        make_float2(2.f * a[0] - x.x, 2.f * a[1] - x.y);
                }
                if (rb < NN) {
                    float2 x = *(const float2*)(g_x0 + (size_t)rb * CDIM + cc);
                    *(float2*)(g_x2 + (size_t)rb * CDIM + cc) =
                        make_float2(2.f * a[2] - x.x, 2.f * a[3] - x.y);
                }
            }
        }
    }
}

// ---------------- ru = sigmoid(xk @ Wru + bru); emit u and r*states ----------------
__global__ __launch_bounds__(256) void ru_kernel(const float* __restrict__ Wru,
                                                 const float* __restrict__ bru,
                                                 const float* __restrict__ states) {
    int n = blockIdx.x, tid = threadIdx.x;
    __shared__ float xr[3][CDIM];
    {
        const float4* p0 = (const float4*)(g_x0 + (size_t)n * CDIM);
        const float4* p1 = (const float4*)(g_x1 + (size_t)n * CDIM);
        const float4* p2 = (const float4*)(g_x2 + (size_t)n * CDIM);
        for (int i = tid; i < CDIM / 4; i += 256) {
            ((float4*)xr[0])[i] = p0[i];
            ((float4*)xr[1])[i] = p1[i];
            ((float4*)xr[2])[i] = p2[i];
        }
    }
    __syncthreads();

    const int hq = tid & 31, bg = tid >> 5;
    const int h0 = hq * 4;
    float4 acc[4];
    float4 bb = *(const float4*)&bru[h0];
#pragma unroll
    for (int j = 0; j < 4; ++j) acc[j] = bb;

    for (int d = 0; d < DFE; ++d) {
        float4 w0 = *(const float4*)&Wru[(d * 3 + 0) * 128 + h0];
        float4 w1 = *(const float4*)&Wru[(d * 3 + 1) * 128 + h0];
        float4 w2 = *(const float4*)&Wru[(d * 3 + 2) * 128 + h0];
#pragma unroll
        for (int j = 0; j < 4; ++j) {
            int b = bg + 8 * j;
            float x0v = xr[0][d * 32 + b];
            float x1v = xr[1][d * 32 + b];
            float x2v = xr[2][d * 32 + b];
            acc[j].x += x0v * w0.x + x1v * w1.x + x2v * w2.x;
            acc[j].y += x0v * w0.y + x1v * w1.y + x2v * w2.y;
            acc[j].z += x0v * w0.z + x1v * w1.z + x2v * w2.z;
            acc[j].w += x0v * w0.w + x1v * w1.w + x2v * w2.w;
        }
    }

#pragma unroll
    for (int j = 0; j < 4; ++j) {
        int b = bg + 8 * j;
        size_t base = ((size_t)b * NN + n) * HID;
        float4 s4;
        s4.x = sigf(acc[j].x); s4.y = sigf(acc[j].y);
        s4.z = sigf(acc[j].z); s4.w = sigf(acc[j].w);
        if (h0 < 64) {
            float4 sv = *(const float4*)&states[base + h0];
            float4 rs;
            rs.x = s4.x * sv.x; rs.y = s4.y * sv.y;
            rs.z = s4.z * sv.z; rs.w = s4.w * sv.w;
            *(float4*)&g_rs[base + h0] = rs;
        } else {
            *(float4*)&g_u[base + h0 - 64] = s4;
        }
    }
}

// ---------------- c = tanh(xk @ Wc + bc); out = u*s + (1-u)*c ----------------
__global__ __launch_bounds__(256) void out_kernel(const float* __restrict__ Wc,
                                                  const float* __restrict__ bc,
                                                  const float* __restrict__ states,
                                                  float* __restrict__ out) {
    int n = blockIdx.x, tid = threadIdx.x;
    __shared__ float xr[3][CDIM];
    {
        const float4* p0 = (const float4*)(g_x0 + (size_t)n * CDIM);
        const float4* p1 = (const float4*)(g_x1 + (size_t)n * CDIM);
        const float4* p2 = (const float4*)(g_x2 + (size_t)n * CDIM);
        for (int i = tid; i < CDIM / 4; i += 256) {
            ((float4*)xr[0])[i] = p0[i];
            ((float4*)xr[1])[i] = p1[i];
            ((float4*)xr[2])[i] = p2[i];
        }
    }
    __syncthreads();

    const int hq = tid & 15, bg = tid >> 4;
    const int h0 = hq * 4;
    float4 acc[2];
    float4 bb = *(const float4*)&bc[h0];
    acc[0] = bb; acc[1] = bb;

    for (int d = 0; d < DFE; ++d) {
        float4 w0 = *(const float4*)&Wc[(d * 3 + 0) * 64 + h0];
        float4 w1 = *(const float4*)&Wc[(d * 3 + 1) * 64 + h0];
        float4 w2 = *(const float4*)&Wc[(d * 3 + 2) * 64 + h0];
#pragma unroll
        for (int j = 0; j < 2; ++j) {
            int b = bg + 16 * j;
            float x0v = xr[0][d * 32 + b];
            float x1v = xr[1][d * 32 + b];
            float x2v = xr[2][d * 32 + b];
            acc[j].x += x0v * w0.x + x1v * w1.x + x2v * w2.x;
            acc[j].y += x0v * w0.y + x1v * w1.y + x2v * w2.y;
            acc[j].z += x0v * w0.z + x1v * w1.z + x2v * w2.z;
            acc[j].w += x0v * w0.w + x1v * w1.w + x2v * w2.w;
        }
    }

#pragma unroll
    for (int j = 0; j < 2; ++j) {
        int b = bg + 16 * j;
        size_t base = ((size_t)b * NN + n) * HID + h0;
        float4 u4 = *(const float4*)&g_u[base];
        float4 sv = *(const float4*)&states[base];
        float4 o;
        float c0 = tanhf(acc[j].x), c1 = tanhf(acc[j].y),
              c2 = tanhf(acc[j].z), c3 = tanhf(acc[j].w);
        o.x = u4.x * sv.x + (1.f - u4.x) * c0;
        o.y = u4.y * sv.y + (1.f - u4.y) * c1;
        o.z = u4.z * sv.z + (1.f - u4.z) * c2;
        o.w = u4.w * sv.w + (1.f - u4.w) * c3;
        *(float4*)&out[base] = o;
    }
}

// ---------------- launcher ----------------
extern "C" void kernel_launch(void* const* d_in, const int* in_sizes, int n_in,
                              void* d_out, int out_size) {
    const float *inputs = nullptr, *states = nullptr, *A = nullptr;
    const float *Wru = nullptr, *bru = nullptr, *Wc = nullptr, *bc = nullptr;
    for (int i = 0; i < n_in; ++i) {
        const float* p = (const float*)d_in[i];
        switch (in_sizes[i]) {
            case 640000:    inputs = p; break;
            case 20480000:  states = p; break;
            case 100000000: A      = p; break;
            case 25344:     Wru    = p; break;
            case 128:       bru    = p; break;
            case 12672:     Wc     = p; break;
            case 64:        bc     = p; break;
            default: break;
        }
    }
    float* out = (float*)d_out;

    const int SMEMSZ = 3 * STAGE_BYTES;   // 98304 -> 2 CTAs/SM
    cudaFuncSetAttribute(gemm_mma<0>, cudaFuncAttributeMaxDynamicSharedMemorySize, SMEMSZ);
    cudaFuncSetAttribute(gemm_mma<1>, cudaFuncAttributeMaxDynamicSharedMemorySize, SMEMSZ);

    conv_A<<<dim3(10, NN), 256>>>(A);
    build_x0_k<<<NN, 256>>>(inputs, states);

    dim3 g(CPAD / 128, MPAD / 128);       // 18 x 79
    gemm_mma<0><<<g, 256, SMEMSZ>>>();    // x1 = A @ x0   (+ bf16 copy)
    gemm_mma<1><<<g, 256, SMEMSZ>>>();    // x2 = 2*A@x1 - x0
    ru_kernel<<<NN, 256>>>(Wru, bru, states);
    update_x0_k<<<NN, 256>>>();
    gemm_mma<0><<<g, 256, SMEMSZ>>>();    // x1' (+ bf16 copy)
    gemm_mma<1><<<g, 256, SMEMSZ>>>();    // x2'
    out_kernel<<<NN, 256>>>(Wc, bc, states, out);
}

// round 16
// speedup vs baseline: 1.1641x; 1.0129x over previous
#include <cuda_runtime.h>
#include <cuda_bf16.h>
#include <cstdint>
#include <cstddef>

#define NN    10000
#define KP    10048          // 157 * 64  (K padded)
#define MPAD  10112          // 79 * 128  (M padded)
#define CPAD  2304           // 18 * 128  (feature dim padded)
#define CDIM  2112           // 66 * 32
#define KT_   157
#define BATCH 32
#define HID   64
#define DFE   66
#define STAGE_BYTES 32768    // A 16KB + B 16KB

// ---------------- scratch (__device__ globals; zero-initialized; pads never written) ----------------
__device__ __nv_bfloat16 g_Abf[(size_t)MPAD * KP];    // A bf16 [m][k]
__device__ __nv_bfloat16 g_Xa [(size_t)KP * CPAD];    // X bf16 [k][c]   (gconv input)
__device__ __nv_bfloat16 g_Xb [(size_t)KP * CPAD];    // A@X bf16 [k][c]
__device__ float g_x0[(size_t)NN * CDIM];
__device__ float g_x1[(size_t)NN * CDIM];
__device__ float g_x2[(size_t)NN * CDIM];
__device__ float g_u [(size_t)BATCH * NN * HID];
__device__ float g_rs[(size_t)BATCH * NN * HID];

// ---------------- helpers ----------------
__device__ __forceinline__ uint32_t s2u(const void* p) {
    uint32_t a;
    asm("{ .reg .u64 t; cvta.to.shared.u64 t, %1; cvt.u32.u64 %0, t; }" : "=r"(a) : "l"(p));
    return a;
}
__device__ __forceinline__ void cp16(uint32_t dst, const void* src) {
    asm volatile("cp.async.cg.shared.global [%0], [%1], 16;\n" :: "r"(dst), "l"(src));
}
__device__ __forceinline__ void cp_commit() { asm volatile("cp.async.commit_group;\n"); }
template <int N>
__device__ __forceinline__ void cp_wait() { asm volatile("cp.async.wait_group %0;\n" :: "n"(N)); }

__device__ __forceinline__ void ldsm4(uint32_t* r, uint32_t addr) {
    asm volatile("ldmatrix.sync.aligned.m8n8.x4.shared.b16 {%0,%1,%2,%3}, [%4];"
                 : "=r"(r[0]), "=r"(r[1]), "=r"(r[2]), "=r"(r[3]) : "r"(addr));
}
__device__ __forceinline__ void ldsm4t(uint32_t& r0, uint32_t& r1, uint32_t& r2, uint32_t& r3,
                                       uint32_t addr) {
    asm volatile("ldmatrix.sync.aligned.m8n8.x4.trans.shared.b16 {%0,%1,%2,%3}, [%4];"
                 : "=r"(r0), "=r"(r1), "=r"(r2), "=r"(r3) : "r"(addr));
}
__device__ __forceinline__ void mma16816(float* c, const uint32_t* a, const uint32_t* b) {
    asm volatile("mma.sync.aligned.m16n8k16.row.col.f32.bf16.bf16.f32 "
                 "{%0,%1,%2,%3}, {%4,%5,%6,%7}, {%8,%9}, {%0,%1,%2,%3};"
                 : "+f"(c[0]), "+f"(c[1]), "+f"(c[2]), "+f"(c[3])
                 : "r"(a[0]), "r"(a[1]), "r"(a[2]), "r"(a[3]), "r"(b[0]), "r"(b[1]));
}
__device__ __forceinline__ float sigf(float x) { return 1.f / (1.f + __expf(-x)); }

// ---- packed f32x2 ----
typedef unsigned long long ull;
__device__ __forceinline__ ull pk2(float a) {
    ull r; asm("mov.b64 %0, {%1,%1};" : "=l"(r) : "f"(a)); return r;
}
__device__ __forceinline__ ull pkab(float a, float b) {
    ull r; asm("mov.b64 %0, {%1,%2};" : "=l"(r) : "f"(a), "f"(b)); return r;
}
__device__ __forceinline__ void f2fma(ull& acc, ull a, ull b) {
    asm("fma.rn.f32x2 %0, %1, %2, %0;" : "+l"(acc) : "l"(a), "l"(b));
}
__device__ __forceinline__ void unpk(ull v, float& a, float& b) {
    asm("mov.b64 {%0,%1}, %2;" : "=f"(a), "=f"(b) : "l"(v));
}

// ---------------- K1: A fp32 -> bf16 (stride KP; pads stay zero) ----------------
__global__ void conv_A(const float* __restrict__ A) {
    int m = blockIdx.y;
    int x4 = blockIdx.x * blockDim.x + threadIdx.x;   // 0..2559
    if (x4 >= NN / 4) return;
    float4 f = ((const float4*)(A + (size_t)m * NN))[x4];
    __nv_bfloat162* dst = (__nv_bfloat162*)(g_Abf + (size_t)m * KP + x4 * 4);
    dst[0] = __floats2bfloat162_rn(f.x, f.y);
    dst[1] = __floats2bfloat162_rn(f.z, f.w);
}

// ---------------- build g_x0 fp32 [n][c] and g_Xa bf16 [n][c] ----------------
__global__ void build_x0_k(const float* __restrict__ inputs, const float* __restrict__ states) {
    int n = blockIdx.x, tid = threadIdx.x;
    __shared__ float s[64][33];
    for (int i = tid; i < BATCH * HID; i += 256) {
        int b = i >> 6, h = i & 63;
        s[h][b] = states[((size_t)b * NN + n) * HID + h];
    }
    __syncthreads();
    size_t r0 = (size_t)n * CDIM, r1 = (size_t)n * CPAD;
    for (int c = tid; c < CDIM; c += 256) {
        int d = c >> 5, b = c & 31;
        float v = (d < 2) ? inputs[((size_t)b * NN + n) * 2 + d] : s[d - 2][b];
        g_x0[r0 + c] = v;
        g_Xa[r1 + c] = __float2bfloat16(v);
    }
}

// ---------------- update state cols of g_x0/g_Xa from g_rs ----------------
__global__ void update_x0_k() {
    int n = blockIdx.x, tid = threadIdx.x;
    __shared__ float s[64][33];
    for (int i = tid; i < BATCH * HID; i += 256) {
        int b = i >> 6, h = i & 63;
        s[h][b] = g_rs[((size_t)b * NN + n) * HID + h];
    }
    __syncthreads();
    size_t r0 = (size_t)n * CDIM, r1 = (size_t)n * CPAD;
    for (int c = 64 + tid; c < CDIM; c += 256) {
        int d = c >> 5, b = c & 31;
        float v = s[d - 2][b];
        g_x0[r0 + c] = v;
        g_Xa[r1 + c] = __float2bfloat16(v);
    }
}

// ---------------- mma.sync GEMM: D[128 x 128] tile of A @ X, 2 CTAs/SM ----------------
// Pipeline (R14-proven order, single barrier):
//   cp_wait<1>  : this thread's group kt retired (in-order)
//   __syncthreads : publishes ALL threads' stage-kt data; also orders
//                   compute(kt-1) before the stage-(kt-1)%3 overwrite below
//   load_stage(kt+2) or empty commit (keeps group count aligned for the tail)
//   compute(kt)
// MODE 0: X = g_Xa; writes fp32 -> g_x1 and bf16 -> g_Xb
// MODE 1: X = g_Xb; writes (2*acc - g_x0) -> g_x2
template <int MODE>
__global__ __launch_bounds__(256, 2) void gemm_mma() {
    extern __shared__ char dyn[];
    const __nv_bfloat16* __restrict__ Xsrc = (MODE == 0) ? g_Xa : g_Xb;

    const int tid = threadIdx.x;
    const int wid = tid >> 5, lid = tid & 31;
    const int wm = wid >> 2, wn = wid & 3;        // 2 x 4 warp grid, 64x32 warp tiles
    const int m0 = blockIdx.y * 128;
    const int c0 = blockIdx.x * 128;
    const uint32_t sbase = s2u(dyn);

    float acc[4][4][4];
#pragma unroll
    for (int i = 0; i < 4; ++i)
#pragma unroll
        for (int j = 0; j < 4; ++j)
#pragma unroll
            for (int q = 0; q < 4; ++q) acc[i][j][q] = 0.f;

    auto load_stage = [&](int s, int kt) {
        const uint32_t As = sbase + s * STAGE_BYTES;
        const uint32_t Bs = As + 16384;
        const __nv_bfloat16* ap = g_Abf + (size_t)m0 * KP + kt * 64;
        const __nv_bfloat16* bp = Xsrc + (size_t)(kt * 64) * CPAD + c0;
        // A: 128 rows x 8 chunks (16B) = 1024
#pragma unroll
        for (int i = 0; i < 4; ++i) {
            int id = tid + 256 * i;
            int r = id >> 3, c = id & 7;
            cp16(As + r * 128 + (((c ^ (r & 7)) << 4)), ap + (size_t)r * KP + c * 8);
        }
        // B: 64 rows x 16 chunks (16B) = 1024
#pragma unroll
        for (int i = 0; i < 4; ++i) {
            int id = tid + 256 * i;
            int r = id >> 4, c = id & 15;
            cp16(Bs + r * 256 + (((c ^ (r & 7)) << 4)), bp + (size_t)r * CPAD + c * 8);
        }
        cp_commit();
    };

    const int lrow = lid & 15, lchk = lid >> 4;
    const int xr = lrow & 7;

    auto compute = [&](int s) {
        const uint32_t sA = sbase + s * STAGE_BYTES;
        const uint32_t sB = sA + 16384;
#pragma unroll
        for (int kk = 0; kk < 4; ++kk) {
            uint32_t af[4][4];
#pragma unroll
            for (int i = 0; i < 4; ++i) {
                int r = wm * 64 + i * 16 + lrow;
                int c = kk * 2 + lchk;
                ldsm4(af[i], sA + r * 128 + (((c ^ (r & 7)) << 4)));
            }
            uint32_t bf[4][2];
#pragma unroll
            for (int p = 0; p < 2; ++p) {
                int r = kk * 16 + lrow;
                int c = wn * 4 + p * 2 + lchk;
                ldsm4t(bf[2*p][0], bf[2*p][1], bf[2*p+1][0], bf[2*p+1][1],
                       sB + r * 256 + (((c ^ xr) << 4)));
            }
#pragma unroll
            for (int i = 0; i < 4; ++i)
#pragma unroll
                for (int j = 0; j < 4; ++j)
                    mma16816(acc[i][j], af[i], bf[j]);
        }
    };

    // prologue: stages 0,1
    load_stage(0, 0);
    load_stage(1, 1);

    for (int kt = 0; kt < KT_; ++kt) {
        cp_wait<1>();                                  // this thread's group kt retired
        __syncthreads();                               // publish all threads' copies
        if (kt + 2 < KT_) load_stage((kt + 2) % 3, kt + 2);
        else cp_commit();                              // keep group count aligned
        compute(kt % 3);
    }

    // ---------------- fused epilogue ----------------
    const int q = lid >> 2, t4 = lid & 3;
#pragma unroll
    for (int i = 0; i < 4; ++i) {
        const int ra = m0 + wm * 64 + i * 16 + q;   // row for c0,c1
        const int rb = ra + 8;                      // row for c2,c3
#pragma unroll
        for (int j = 0; j < 4; ++j) {
            const int cc = c0 + wn * 32 + j * 8 + t4 * 2;
            if (cc >= CDIM) continue;
            const float* a = acc[i][j];
            if (MODE == 0) {
                if (ra < NN) {
                    *(float2*)(g_x1 + (size_t)ra * CDIM + cc) = make_float2(a[0], a[1]);
                    *(__nv_bfloat162*)(g_Xb + (size_t)ra * CPAD + cc) =
                        __floats2bfloat162_rn(a[0], a[1]);
                }
                if (rb < NN) {
                    *(float2*)(g_x1 + (size_t)rb * CDIM + cc) = make_float2(a[2], a[3]);
                    *(__nv_bfloat162*)(g_Xb + (size_t)rb * CPAD + cc) =
                        __floats2bfloat162_rn(a[2], a[3]);
                }
            } else {
                if (ra < NN) {
                    float2 x = *(const float2*)(g_x0 + (size_t)ra * CDIM + cc);
                    *(float2*)(g_x2 + (size_t)ra * CDIM + cc) =
                        make_float2(2.f * a[0] - x.x, 2.f * a[1] - x.y);
                }
                if (rb < NN) {
                    float2 x = *(const float2*)(g_x0 + (size_t)rb * CDIM + cc);
                    *(float2*)(g_x2 + (size_t)rb * CDIM + cc) =
                        make_float2(2.f * a[2] - x.x, 2.f * a[3] - x.y);
                }
            }
        }
    }
}

// ---------------- ru = sigmoid(xk @ Wru + bru); emit u and r*states  (f32x2) ----------------
__global__ __launch_bounds__(256) void ru_kernel(const float* __restrict__ Wru,
                                                 const float* __restrict__ bru,
                                                 const float* __restrict__ states) {
    int n = blockIdx.x, tid = threadIdx.x;
    __shared__ float xr[3][CDIM];
    {
        const float4* p0 = (const float4*)(g_x0 + (size_t)n * CDIM);
        const float4* p1 = (const float4*)(g_x1 + (size_t)n * CDIM);
        const float4* p2 = (const float4*)(g_x2 + (size_t)n * CDIM);
        for (int i = tid; i < CDIM / 4; i += 256) {
            ((float4*)xr[0])[i] = p0[i];
            ((float4*)xr[1])[i] = p1[i];
            ((float4*)xr[2])[i] = p2[i];
        }
    }
    __syncthreads();

    const int hq = tid & 31, bg = tid >> 5;
    const int h0 = hq * 4;
    ull aP[4][2];
    {
        float4 bb = *(const float4*)&bru[h0];
        ull b01 = pkab(bb.x, bb.y), b23 = pkab(bb.z, bb.w);
#pragma unroll
        for (int j = 0; j < 4; ++j) { aP[j][0] = b01; aP[j][1] = b23; }
    }

    for (int d = 0; d < DFE; ++d) {
        float4 w0 = *(const float4*)&Wru[(d * 3 + 0) * 128 + h0];
        float4 w1 = *(const float4*)&Wru[(d * 3 + 1) * 128 + h0];
        float4 w2 = *(const float4*)&Wru[(d * 3 + 2) * 128 + h0];
        ull w0a = pkab(w0.x, w0.y), w0b = pkab(w0.z, w0.w);
        ull w1a = pkab(w1.x, w1.y), w1b = pkab(w1.z, w1.w);
        ull w2a = pkab(w2.x, w2.y), w2b = pkab(w2.z, w2.w);
#pragma unroll
        for (int j = 0; j < 4; ++j) {
            int b = bg + 8 * j;
            ull x0p = pk2(xr[0][d * 32 + b]);
            ull x1p = pk2(xr[1][d * 32 + b]);
            ull x2p = pk2(xr[2][d * 32 + b]);
            f2fma(aP[j][0], w0a, x0p); f2fma(aP[j][1], w0b, x0p);
            f2fma(aP[j][0], w1a, x1p); f2fma(aP[j][1], w1b, x1p);
            f2fma(aP[j][0], w2a, x2p); f2fma(aP[j][1], w2b, x2p);
        }
    }

#pragma unroll
    for (int j = 0; j < 4; ++j) {
        int b = bg + 8 * j;
        size_t base = ((size_t)b * NN + n) * HID;
        float ax, ay, az, aw;
        unpk(aP[j][0], ax, ay); unpk(aP[j][1], az, aw);
        float4 s4;
        s4.x = sigf(ax); s4.y = sigf(ay); s4.z = sigf(az); s4.w = sigf(aw);
        if (h0 < 64) {
            float4 sv = *(const float4*)&states[base + h0];
            float4 rs;
            rs.x = s4.x * sv.x; rs.y = s4.y * sv.y;
            rs.z = s4.z * sv.z; rs.w = s4.w * sv.w;
            *(float4*)&g_rs[base + h0] = rs;
        } else {
            *(float4*)&g_u[base + h0 - 64] = s4;
        }
    }
}

// ---------------- c = tanh(xk @ Wc + bc); out = u*s + (1-u)*c  (f32x2) ----------------
__global__ __launch_bounds__(256) void out_kernel(const float* __restrict__ Wc,
                                                  const float* __restrict__ bc,
                                                  const float* __restrict__ states,
                                                  float* __restrict__ out) {
    int n = blockIdx.x, tid = threadIdx.x;
    __shared__ float xr[3][CDIM];
    {
        const float4* p0 = (const float4*)(g_x0 + (size_t)n * CDIM);
        const float4* p1 = (const float4*)(g_x1 + (size_t)n * CDIM);
        const float4* p2 = (const float4*)(g_x2 + (size_t)n * CDIM);
        for (int i = tid; i < CDIM / 4; i += 256) {
            ((float4*)xr[0])[i] = p0[i];
            ((float4*)xr[1])[i] = p1[i];
            ((float4*)xr[2])[i] = p2[i];
        }
    }
    __syncthreads();

    const int hq = tid & 15, bg = tid >> 4;
    const int h0 = hq * 4;
    ull aP[2][2];
    {
        float4 bb = *(const float4*)&bc[h0];
        ull b01 = pkab(bb.x, bb.y), b23 = pkab(bb.z, bb.w);
        aP[0][0] = b01; aP[0][1] = b23;
        aP[1][0] = b01; aP[1][1] = b23;
    }

    for (int d = 0; d < DFE; ++d) {
        float4 w0 = *(const float4*)&Wc[(d * 3 + 0) * 64 + h0];
        float4 w1 = *(const float4*)&Wc[(d * 3 + 1) * 64 + h0];
        float4 w2 = *(const float4*)&Wc[(d * 3 + 2) * 64 + h0];
        ull w0a = pkab(w0.x, w0.y), w0b = pkab(w0.z, w0.w);
        ull w1a = pkab(w1.x, w1.y), w1b = pkab(w1.z, w1.w);
        ull w2a = pkab(w2.x, w2.y), w2b = pkab(w2.z, w2.w);
#pragma unroll
        for (int j = 0; j < 2; ++j) {
            int b = bg + 16 * j;
            ull x0p = pk2(xr[0][d * 32 + b]);
            ull x1p = pk2(xr[1][d * 32 + b]);
            ull x2p = pk2(xr[2][d * 32 + b]);
            f2fma(aP[j][0], w0a, x0p); f2fma(aP[j][1], w0b, x0p);
            f2fma(aP[j][0], w1a, x1p); f2fma(aP[j][1], w1b, x1p);
            f2fma(aP[j][0], w2a, x2p); f2fma(aP[j][1], w2b, x2p);
        }
    }

#pragma unroll
    for (int j = 0; j < 2; ++j) {
        int b = bg + 16 * j;
        size_t base = ((size_t)b * NN + n) * HID + h0;
        float4 u4 = *(const float4*)&g_u[base];
        float4 sv = *(const float4*)&states[base];
        float ax, ay, az, aw;
        unpk(aP[j][0], ax, ay); unpk(aP[j][1], az, aw);
        float4 o;
        float c0 = tanhf(ax), c1 = tanhf(ay), c2 = tanhf(az), c3 = tanhf(aw);
        o.x = u4.x * sv.x + (1.f - u4.x) * c0;
        o.y = u4.y * sv.y + (1.f - u4.y) * c1;
        o.z = u4.z * sv.z + (1.f - u4.z) * c2;
        o.w = u4.w * sv.w + (1.f - u4.w) * c3;
        *(float4*)&out[base] = o;
    }
}

// ---------------- launcher ----------------
extern "C" void kernel_launch(void* const* d_in, const int* in_sizes, int n_in,
                              void* d_out, int out_size) {
    const float *inputs = nullptr, *states = nullptr, *A = nullptr;
    const float *Wru = nullptr, *bru = nullptr, *Wc = nullptr, *bc = nullptr;
    for (int i = 0; i < n_in; ++i) {
        const float* p = (const float*)d_in[i];
        switch (in_sizes[i]) {
            case 640000:    inputs = p; break;
            case 20480000:  states = p; break;
            case 100000000: A      = p; break;
            case 25344:     Wru    = p; break;
            case 128:       bru    = p; break;
            case 12672:     Wc     = p; break;
            case 64:        bc     = p; break;
            default: break;
        }
    }
    float* out = (float*)d_out;

    const int SMEMSZ = 3 * STAGE_BYTES;   // 98304 -> 2 CTAs/SM
    cudaFuncSetAttribute(gemm_mma<0>, cudaFuncAttributeMaxDynamicSharedMemorySize, SMEMSZ);
    cudaFuncSetAttribute(gemm_mma<1>, cudaFuncAttributeMaxDynamicSharedMemorySize, SMEMSZ);

    conv_A<<<dim3(10, NN), 256>>>(A);
    build_x0_k<<<NN, 256>>>(inputs, states);

    dim3 g(CPAD / 128, MPAD / 128);       // 18 x 79
    gemm_mma<0><<<g, 256, SMEMSZ>>>();    // x1 = A @ x0   (+ bf16 copy)
    gemm_mma<1><<<g, 256, SMEMSZ>>>();    // x2 = 2*A@x1 - x0
    ru_kernel<<<NN, 256>>>(Wru, bru, states);
    update_x0_k<<<NN, 256>>>();
    gemm_mma<0><<<g, 256, SMEMSZ>>>();    // x1' (+ bf16 copy)
    gemm_mma<1><<<g, 256, SMEMSZ>>>();    // x2'
    out_kernel<<<NN, 256>>>(Wc, bc, states, out);
}

// round 17
// speedup vs baseline: 1.1751x; 1.0095x over previous
#include <cuda_runtime.h>
#include <cuda_bf16.h>
#include <cstdint>
#include <cstddef>

#define NN    10000
#define KP    10048          // 157 * 64  (K padded)
#define MPAD  10112          // 79 * 128  (M padded)
#define CPAD  2304           // feature dim padded (>= 2112)
#define CDIM  2112           // 66 * 32
#define KT_   157
#define BATCH 32
#define HID   64
#define DFE   66
#define STAGE_BYTES 32768    // A 16KB + B 16KB (64 rows x 256B, 12/16 chunks used)

// ---------------- scratch (__device__ globals; zero-initialized; pads never written) ----------------
__device__ __nv_bfloat16 g_Abf[(size_t)MPAD * KP];    // A bf16 [m][k]
__device__ __nv_bfloat16 g_Xa [(size_t)KP * CPAD];    // X bf16 [k][c]   (gconv input)
__device__ __nv_bfloat16 g_Xb [(size_t)KP * CPAD];    // A@X bf16 [k][c]
__device__ float g_x0[(size_t)NN * CDIM];
__device__ float g_x1[(size_t)NN * CDIM];
__device__ float g_x2[(size_t)NN * CDIM];
__device__ float g_u [(size_t)BATCH * NN * HID];
__device__ float g_rs[(size_t)BATCH * NN * HID];

// ---------------- helpers ----------------
__device__ __forceinline__ uint32_t s2u(const void* p) {
    uint32_t a;
    asm("{ .reg .u64 t; cvta.to.shared.u64 t, %1; cvt.u32.u64 %0, t; }" : "=r"(a) : "l"(p));
    return a;
}
__device__ __forceinline__ void cp16(uint32_t dst, const void* src) {
    asm volatile("cp.async.cg.shared.global [%0], [%1], 16;\n" :: "r"(dst), "l"(src));
}
__device__ __forceinline__ void cp_commit() { asm volatile("cp.async.commit_group;\n"); }
template <int N>
__device__ __forceinline__ void cp_wait() { asm volatile("cp.async.wait_group %0;\n" :: "n"(N)); }

__device__ __forceinline__ void ldsm4(uint32_t* r, uint32_t addr) {
    asm volatile("ldmatrix.sync.aligned.m8n8.x4.shared.b16 {%0,%1,%2,%3}, [%4];"
                 : "=r"(r[0]), "=r"(r[1]), "=r"(r[2]), "=r"(r[3]) : "r"(addr));
}
__device__ __forceinline__ void ldsm4t(uint32_t& r0, uint32_t& r1, uint32_t& r2, uint32_t& r3,
                                       uint32_t addr) {
    asm volatile("ldmatrix.sync.aligned.m8n8.x4.trans.shared.b16 {%0,%1,%2,%3}, [%4];"
                 : "=r"(r0), "=r"(r1), "=r"(r2), "=r"(r3) : "r"(addr));
}
__device__ __forceinline__ void mma16816(float* c, const uint32_t* a, const uint32_t* b) {
    asm volatile("mma.sync.aligned.m16n8k16.row.col.f32.bf16.bf16.f32 "
                 "{%0,%1,%2,%3}, {%4,%5,%6,%7}, {%8,%9}, {%0,%1,%2,%3};"
                 : "+f"(c[0]), "+f"(c[1]), "+f"(c[2]), "+f"(c[3])
                 : "r"(a[0]), "r"(a[1]), "r"(a[2]), "r"(a[3]), "r"(b[0]), "r"(b[1]));
}
__device__ __forceinline__ float sigf(float x) { return 1.f / (1.f + __expf(-x)); }

// ---- packed f32x2 ----
typedef unsigned long long ull;
__device__ __forceinline__ ull pk2(float a) {
    ull r; asm("mov.b64 %0, {%1,%1};" : "=l"(r) : "f"(a)); return r;
}
__device__ __forceinline__ ull pkab(float a, float b) {
    ull r; asm("mov.b64 %0, {%1,%2};" : "=l"(r) : "f"(a), "f"(b)); return r;
}
__device__ __forceinline__ void f2fma(ull& acc, ull a, ull b) {
    asm("fma.rn.f32x2 %0, %1, %2, %0;" : "+l"(acc) : "l"(a), "l"(b));
}
__device__ __forceinline__ void unpk(ull v, float& a, float& b) {
    asm("mov.b64 {%0,%1}, %2;" : "=f"(a), "=f"(b) : "l"(v));
}

// ---------------- K1: A fp32 -> bf16 (stride KP; pads stay zero) ----------------
__global__ void conv_A(const float* __restrict__ A) {
    int m = blockIdx.y;
    int x4 = blockIdx.x * blockDim.x + threadIdx.x;   // 0..2559
    if (x4 >= NN / 4) return;
    float4 f = ((const float4*)(A + (size_t)m * NN))[x4];
    __nv_bfloat162* dst = (__nv_bfloat162*)(g_Abf + (size_t)m * KP + x4 * 4);
    dst[0] = __floats2bfloat162_rn(f.x, f.y);
    dst[1] = __floats2bfloat162_rn(f.z, f.w);
}

// ---------------- build g_x0 fp32 [n][c] and g_Xa bf16 [n][c] ----------------
__global__ void build_x0_k(const float* __restrict__ inputs, const float* __restrict__ states) {
    int n = blockIdx.x, tid = threadIdx.x;
    __shared__ float s[64][33];
    for (int i = tid; i < BATCH * HID; i += 256) {
        int b = i >> 6, h = i & 63;
        s[h][b] = states[((size_t)b * NN + n) * HID + h];
    }
    __syncthreads();
    size_t r0 = (size_t)n * CDIM, r1 = (size_t)n * CPAD;
    for (int c = tid; c < CDIM; c += 256) {
        int d = c >> 5, b = c & 31;
        float v = (d < 2) ? inputs[((size_t)b * NN + n) * 2 + d] : s[d - 2][b];
        g_x0[r0 + c] = v;
        g_Xa[r1 + c] = __float2bfloat16(v);
    }
}

// ---------------- update state cols of g_x0/g_Xa from g_rs ----------------
__global__ void update_x0_k() {
    int n = blockIdx.x, tid = threadIdx.x;
    __shared__ float s[64][33];
    for (int i = tid; i < BATCH * HID; i += 256) {
        int b = i >> 6, h = i & 63;
        s[h][b] = g_rs[((size_t)b * NN + n) * HID + h];
    }
    __syncthreads();
    size_t r0 = (size_t)n * CDIM, r1 = (size_t)n * CPAD;
    for (int c = 64 + tid; c < CDIM; c += 256) {
        int d = c >> 5, b = c & 31;
        float v = s[d - 2][b];
        g_x0[r0 + c] = v;
        g_Xa[r1 + c] = __float2bfloat16(v);
    }
}

// ---------------- mma.sync GEMM: D[128 x 96] tile of A @ X, 2 CTAs/SM ----------------
// BN=96: 2112 = 22*96 exactly (no N-pad waste); 22*79 = 1738 tiles -> 5.87 waves
// (vs 4.80->5 with BN=128), cutting wave-quantization + pad waste ~10%.
// Warp grid 4x2, warp tile 32x48 (acc 48 regs).
// B stage rows padded to 256B (chunks 0..11 of 16 used) so the xor-swizzle
// stays closed under c^(r&7) (maps 0..15 -> 0..15; reads only touch written c<12).
// Pipeline identical to R16 (proven): wait<1> -> syncthreads -> load(kt+2)|commit -> compute.
// MODE 0: X = g_Xa; writes fp32 -> g_x1 and bf16 -> g_Xb
// MODE 1: X = g_Xb; writes (2*acc - g_x0) -> g_x2
template <int MODE>
__global__ __launch_bounds__(256, 2) void gemm_mma() {
    extern __shared__ char dyn[];
    const __nv_bfloat16* __restrict__ Xsrc = (MODE == 0) ? g_Xa : g_Xb;

    const int tid = threadIdx.x;
    const int wid = tid >> 5, lid = tid & 31;
    const int wm = wid >> 1, wn = wid & 1;        // 4 x 2 warp grid, 32x48 warp tiles
    const int m0 = blockIdx.y * 128;
    const int c0 = blockIdx.x * 96;
    const uint32_t sbase = s2u(dyn);

    float acc[2][6][4];
#pragma unroll
    for (int i = 0; i < 2; ++i)
#pragma unroll
        for (int j = 0; j < 6; ++j)
#pragma unroll
            for (int q = 0; q < 4; ++q) acc[i][j][q] = 0.f;

    auto load_stage = [&](int s, int kt) {
        const uint32_t As = sbase + s * STAGE_BYTES;
        const uint32_t Bs = As + 16384;
        const __nv_bfloat16* ap = g_Abf + (size_t)m0 * KP + kt * 64;
        const __nv_bfloat16* bp = Xsrc + (size_t)(kt * 64) * CPAD + c0;
        // A: 128 rows x 8 chunks (16B) = 1024
#pragma unroll
        for (int i = 0; i < 4; ++i) {
            int id = tid + 256 * i;
            int r = id >> 3, c = id & 7;
            cp16(As + r * 128 + (((c ^ (r & 7)) << 4)), ap + (size_t)r * KP + c * 8);
        }
        // B: 64 rows x 12 chunks (16B) = 768 active (of 1024 slots)
#pragma unroll
        for (int i = 0; i < 4; ++i) {
            int id = tid + 256 * i;
            int r = id >> 4, c = id & 15;
            if (c < 12)
                cp16(Bs + r * 256 + (((c ^ (r & 7)) << 4)), bp + (size_t)r * CPAD + c * 8);
        }
        cp_commit();
    };

    const int lrow = lid & 15, lchk = lid >> 4;
    const int xr = lrow & 7;

    auto compute = [&](int s) {
        const uint32_t sA = sbase + s * STAGE_BYTES;
        const uint32_t sB = sA + 16384;
#pragma unroll
        for (int kk = 0; kk < 4; ++kk) {
            uint32_t af[2][4];
#pragma unroll
            for (int i = 0; i < 2; ++i) {
                int r = wm * 32 + i * 16 + lrow;
                int c = kk * 2 + lchk;
                ldsm4(af[i], sA + r * 128 + (((c ^ (r & 7)) << 4)));
            }
            uint32_t bf[6][2];
#pragma unroll
            for (int p = 0; p < 3; ++p) {
                int r = kk * 16 + lrow;
                int c = wn * 6 + p * 2 + lchk;
                ldsm4t(bf[2*p][0], bf[2*p][1], bf[2*p+1][0], bf[2*p+1][1],
                       sB + r * 256 + (((c ^ xr) << 4)));
            }
#pragma unroll
            for (int i = 0; i < 2; ++i)
#pragma unroll
                for (int j = 0; j < 6; ++j)
                    mma16816(acc[i][j], af[i], bf[j]);
        }
    };

    // prologue: stages 0,1
    load_stage(0, 0);
    load_stage(1, 1);

    for (int kt = 0; kt < KT_; ++kt) {
        cp_wait<1>();                                  // this thread's group kt retired
        __syncthreads();                               // publish all threads' copies
        if (kt + 2 < KT_) load_stage((kt + 2) % 3, kt + 2);
        else cp_commit();                              // keep group count aligned
        compute(kt % 3);
    }

    // ---------------- fused epilogue ----------------
    const int q = lid >> 2, t4 = lid & 3;
#pragma unroll
    for (int i = 0; i < 2; ++i) {
        const int ra = m0 + wm * 32 + i * 16 + q;   // row for c0,c1
        const int rb = ra + 8;                      // row for c2,c3
#pragma unroll
        for (int j = 0; j < 6; ++j) {
            const int cc = c0 + wn * 48 + j * 8 + t4 * 2;
            if (cc >= CDIM) continue;
            const float* a = acc[i][j];
            if (MODE == 0) {
                if (ra < NN) {
                    *(float2*)(g_x1 + (size_t)ra * CDIM + cc) = make_float2(a[0], a[1]);
                    *(__nv_bfloat162*)(g_Xb + (size_t)ra * CPAD + cc) =
                        __floats2bfloat162_rn(a[0], a[1]);
                }
                if (rb < NN) {
                    *(float2*)(g_x1 + (size_t)rb * CDIM + cc) = make_float2(a[2], a[3]);
                    *(__nv_bfloat162*)(g_Xb + (size_t)rb * CPAD + cc) =
                        __floats2bfloat162_rn(a[2], a[3]);
                }
            } else {
                if (ra < NN) {
                    float2 x = *(const float2*)(g_x0 + (size_t)ra * CDIM + cc);
                    *(float2*)(g_x2 + (size_t)ra * CDIM + cc) =
                        make_float2(2.f * a[0] - x.x, 2.f * a[1] - x.y);
                }
                if (rb < NN) {
                    float2 x = *(const float2*)(g_x0 + (size_t)rb * CDIM + cc);
                    *(float2*)(g_x2 + (size_t)rb * CDIM + cc) =
                        make_float2(2.f * a[2] - x.x, 2.f * a[3] - x.y);
                }
            }
        }
    }
}

// ---------------- ru = sigmoid(xk @ Wru + bru); emit u and r*states  (f32x2) ----------------
__global__ __launch_bounds__(256) void ru_kernel(const float* __restrict__ Wru,
                                                 const float* __restrict__ bru,
                                                 const float* __restrict__ states) {
    int n = blockIdx.x, tid = threadIdx.x;
    __shared__ float xr[3][CDIM];
    {
        const float4* p0 = (const float4*)(g_x0 + (size_t)n * CDIM);
        const float4* p1 = (const float4*)(g_x1 + (size_t)n * CDIM);
        const float4* p2 = (const float4*)(g_x2 + (size_t)n * CDIM);
        for (int i = tid; i < CDIM / 4; i += 256) {
            ((float4*)xr[0])[i] = p0[i];
            ((float4*)xr[1])[i] = p1[i];
            ((float4*)xr[2])[i] = p2[i];
        }
    }
    __syncthreads();

    const int hq = tid & 31, bg = tid >> 5;
    const int h0 = hq * 4;
    ull aP[4][2];
    {
        float4 bb = *(const float4*)&bru[h0];
        ull b01 = pkab(bb.x, bb.y), b23 = pkab(bb.z, bb.w);
#pragma unroll
        for (int j = 0; j < 4; ++j) { aP[j][0] = b01; aP[j][1] = b23; }
    }

    for (int d = 0; d < DFE; ++d) {
        float4 w0 = *(const float4*)&Wru[(d * 3 + 0) * 128 + h0];
        float4 w1 = *(const float4*)&Wru[(d * 3 + 1) * 128 + h0];
        float4 w2 = *(const float4*)&Wru[(d * 3 + 2) * 128 + h0];
        ull w0a = pkab(w0.x, w0.y), w0b = pkab(w0.z, w0.w);
        ull w1a = pkab(w1.x, w1.y), w1b = pkab(w1.z, w1.w);
        ull w2a = pkab(w2.x, w2.y), w2b = pkab(w2.z, w2.w);
#pragma unroll
        for (int j = 0; j < 4; ++j) {
            int b = bg + 8 * j;
            ull x0p = pk2(xr[0][d * 32 + b]);
            ull x1p = pk2(xr[1][d * 32 + b]);
            ull x2p = pk2(xr[2][d * 32 + b]);
            f2fma(aP[j][0], w0a, x0p); f2fma(aP[j][1], w0b, x0p);
            f2fma(aP[j][0], w1a, x1p); f2fma(aP[j][1], w1b, x1p);
            f2fma(aP[j][0], w2a, x2p); f2fma(aP[j][1], w2b, x2p);
        }
    }

#pragma unroll
    for (int j = 0; j < 4; ++j) {
        int b = bg + 8 * j;
        size_t base = ((size_t)b * NN + n) * HID;
        float ax, ay, az, aw;
        unpk(aP[j][0], ax, ay); unpk(aP[j][1], az, aw);
        float4 s4;
        s4.x = sigf(ax); s4.y = sigf(ay); s4.z = sigf(az); s4.w = sigf(aw);
        if (h0 < 64) {
            float4 sv = *(const float4*)&states[base + h0];
            float4 rs;
            rs.x = s4.x * sv.x; rs.y = s4.y * sv.y;
            rs.z = s4.z * sv.z; rs.w = s4.w * sv.w;
            *(float4*)&g_rs[base + h0] = rs;
        } else {
            *(float4*)&g_u[base + h0 - 64] = s4;
        }
    }
}

// ---------------- c = tanh(xk @ Wc + bc); out = u*s + (1-u)*c  (f32x2) ----------------
__global__ __launch_bounds__(256) void out_kernel(const float* __restrict__ Wc,
                                                  const float* __restrict__ bc,
                                                  const float* __restrict__ states,
                                                  float* __restrict__ out) {
    int n = blockIdx.x, tid = threadIdx.x;
    __shared__ float xr[3][CDIM];
    {
        const float4* p0 = (const float4*)(g_x0 + (size_t)n * CDIM);
        const float4* p1 = (const float4*)(g_x1 + (size_t)n * CDIM);
        const float4* p2 = (const float4*)(g_x2 + (size_t)n * CDIM);
        for (int i = tid; i < CDIM / 4; i += 256) {
            ((float4*)xr[0])[i] = p0[i];
            ((float4*)xr[1])[i] = p1[i];
            ((float4*)xr[2])[i] = p2[i];
        }
    }
    __syncthreads();

    const int hq = tid & 15, bg = tid >> 4;
    const int h0 = hq * 4;
    ull aP[2][2];
    {
        float4 bb = *(const float4*)&bc[h0];
        ull b01 = pkab(bb.x, bb.y), b23 = pkab(bb.z, bb.w);
        aP[0][0] = b01; aP[0][1] = b23;
        aP[1][0] = b01; aP[1][1] = b23;
    }

    for (int d = 0; d < DFE; ++d) {
        float4 w0 = *(const float4*)&Wc[(d * 3 + 0) * 64 + h0];
        float4 w1 = *(const float4*)&Wc[(d * 3 + 1) * 64 + h0];
        float4 w2 = *(const float4*)&Wc[(d * 3 + 2) * 64 + h0];
        ull w0a = pkab(w0.x, w0.y), w0b = pkab(w0.z, w0.w);
        ull w1a = pkab(w1.x, w1.y), w1b = pkab(w1.z, w1.w);
        ull w2a = pkab(w2.x, w2.y), w2b = pkab(w2.z, w2.w);
#pragma unroll
        for (int j = 0; j < 2; ++j) {
            int b = bg + 16 * j;
            ull x0p = pk2(xr[0][d * 32 + b]);
            ull x1p = pk2(xr[1][d * 32 + b]);
            ull x2p = pk2(xr[2][d * 32 + b]);
            f2fma(aP[j][0], w0a, x0p); f2fma(aP[j][1], w0b, x0p);
            f2fma(aP[j][0], w1a, x1p); f2fma(aP[j][1], w1b, x1p);
            f2fma(aP[j][0], w2a, x2p); f2fma(aP[j][1], w2b, x2p);
        }
    }

#pragma unroll
    for (int j = 0; j < 2; ++j) {
        int b = bg + 16 * j;
        size_t base = ((size_t)b * NN + n) * HID + h0;
        float4 u4 = *(const float4*)&g_u[base];
        float4 sv = *(const float4*)&states[base];
        float ax, ay, az, aw;
        unpk(aP[j][0], ax, ay); unpk(aP[j][1], az, aw);
        float4 o;
        float c0 = tanhf(ax), c1 = tanhf(ay), c2 = tanhf(az), c3 = tanhf(aw);
        o.x = u4.x * sv.x + (1.f - u4.x) * c0;
        o.y = u4.y * sv.y + (1.f - u4.y) * c1;
        o.z = u4.z * sv.z + (1.f - u4.z) * c2;
        o.w = u4.w * sv.w + (1.f - u4.w) * c3;
        *(float4*)&out[base] = o;
    }
}

// ---------------- launcher ----------------
extern "C" void kernel_launch(void* const* d_in, const int* in_sizes, int n_in,
                              void* d_out, int out_size) {
    const float *inputs = nullptr, *states = nullptr, *A = nullptr;
    const float *Wru = nullptr, *bru = nullptr, *Wc = nullptr, *bc = nullptr;
    for (int i = 0; i < n_in; ++i) {
        const float* p = (const float*)d_in[i];
        switch (in_sizes[i]) {
            case 640000:    inputs = p; break;
            case 20480000:  states = p; break;
            case 100000000: A      = p; break;
            case 25344:     Wru    = p; break;
            case 128:       bru    = p; break;
            case 12672:     Wc     = p; break;
            case 64:        bc     = p; break;
            default: break;
        }
    }
    float* out = (float*)d_out;

    const int SMEMSZ = 3 * STAGE_BYTES;   // 98304 -> 2 CTAs/SM
    cudaFuncSetAttribute(gemm_mma<0>, cudaFuncAttributeMaxDynamicSharedMemorySize, SMEMSZ);
    cudaFuncSetAttribute(gemm_mma<1>, cudaFuncAttributeMaxDynamicSharedMemorySize, SMEMSZ);

    conv_A<<<dim3(10, NN), 256>>>(A);
    build_x0_k<<<NN, 256>>>(inputs, states);

    dim3 g(22, MPAD / 128);               // 22 x 79 (2112 = 22*96 exact)
    gemm_mma<0><<<g, 256, SMEMSZ>>>();    // x1 = A @ x0   (+ bf16 copy)
    gemm_mma<1><<<g, 256, SMEMSZ>>>();    // x2 = 2*A@x1 - x0
    ru_kernel<<<NN, 256>>>(Wru, bru, states);
    update_x0_k<<<NN, 256>>>();
    gemm_mma<0><<<g, 256, SMEMSZ>>>();    // x1' (+ bf16 copy)
    gemm_mma<1><<<g, 256, SMEMSZ>>>();    // x2'
    out_kernel<<<NN, 256>>>(Wc, bc, states, out);
}